// round 14
// baseline (speedup 1.0000x reference)
#include <cuda_runtime.h>
#include <math.h>

// Fixed problem shapes
#define NN 100000
#define DD 256
#define EE 200000
#define BB 50000
#define WDECAY 1e-6f
#define ROW4 (DD / 4)   // 64 float4 per row
#define CAP 48          // max incident edges per node (Poisson(4); P(>48) ~ 0)
#define NGRP ((BB + 15) / 16 + 2)

// Scratch (device globals — no runtime allocation allowed)
__device__ int   g_deg[NN];
__device__ int2  g_adj[(size_t)NN * CAP];        // {opp_node, float_bits(tw)}
__device__ uint4 g_featf[(size_t)NGRP * 8 * 32]; // feat in A-fragment tf32 layout
__device__ uint2 g_w1f[256 * 32];                // w1 B-fragments
__device__ uint2 g_w2f[256 * 32];                // w2 B-fragments

__device__ __forceinline__ float4 f4s(float4 a, float s) {
    return make_float4(a.x * s, a.y * s, a.z * s, a.w * s);
}

__device__ __forceinline__ unsigned f2tf32(float x) {
    unsigned r;
    asm("cvt.rna.tf32.f32 %0, %1;" : "=r"(r) : "f"(x));
    return r;
}

#define MMA_TF32(d0, d1, d2, d3, a0, a1, a2, a3, b0, b1)                     \
    asm("mma.sync.aligned.m16n8k8.row.col.f32.tf32.tf32.f32 "                \
        "{%0,%1,%2,%3}, {%4,%5,%6,%7}, {%8,%9}, {%0,%1,%2,%3};"              \
        : "+f"(d0), "+f"(d1), "+f"(d2), "+f"(d3)                             \
        : "r"(a0), "r"(a1), "r"(a2), "r"(a3), "r"(b0), "r"(b1))

// ---------------------------------------------------------------------------
// k_init: zero g_deg + prep w1/w2 fragments, role by index.
// ---------------------------------------------------------------------------
__global__ void k_init(const float* __restrict__ w1,
                       const float* __restrict__ w2) {
    int i = blockIdx.x * blockDim.x + threadIdx.x;
    if (i < 25000) {
        ((int4*)g_deg)[i] = make_int4(0, 0, 0, 0);
        return;
    }
    i -= 25000;
    if (i >= 512 * 32) return;
    int lane = i & 31, frag = i >> 5;
    int gq = lane >> 2, tq = lane & 3;
    if (frag < 256) {
        int k8 = frag >> 5, nc = frag & 31;
        float b0 = __ldg(w1 + (k8 * 8 + tq) * 256 + nc * 8 + gq);
        float b1 = __ldg(w1 + (k8 * 8 + tq + 4) * 256 + nc * 8 + gq);
        g_w1f[i] = make_uint2(f2tf32(b0), f2tf32(b1));
    } else {
        int f2 = frag - 256;
        int kk = f2 >> 3, n8 = f2 & 7;
        float b0 = __ldg(w2 + (kk * 8 + tq) * 64 + n8 * 8 + gq);
        float b1 = __ldg(w2 + (kk * 8 + tq + 4) * 64 + n8 * 8 + gq);
        g_w2f[f2 * 32 + lane] = make_uint2(f2tf32(b0), f2tf32(b1));
    }
}

// ---------------------------------------------------------------------------
// Build padded adjacency in one pass (scalars folded in)
// ---------------------------------------------------------------------------
__global__ void k_build(const int* __restrict__ src,
                        const int* __restrict__ dst,
                        const float* __restrict__ times, int E) {
    int e = blockIdx.x * blockDim.x + threadIdx.x;
    if (e >= E) return;
    float nt = __ldg(times + E - 1);
    int s = src[e];
    int t = dst[e];
    float w = __expf(-WDECAY * (nt - times[e]));
    int wb = __float_as_int(w);
    int p1 = atomicAdd(&g_deg[s], 1);
    if (p1 < CAP) g_adj[(size_t)s * CAP + p1] = make_int2(t, wb);
    int p2 = atomicAdd(&g_deg[t], 1);
    if (p2 < CAP) g_adj[(size_t)t * CAP + p2] = make_int2(s, wb);
}

// ---------------------------------------------------------------------------
// Fused pair kernel (best-measured body): 64 threads/pair, float4 column
// slices. Computes the 8 updated rows for (s,t) on the fly, Gram + log1p,
// then writes feat directly in A-fragment tf32 layout -> g_featf.
// ---------------------------------------------------------------------------
__device__ const int TRI_I[36] = {0,0,0,0,0,0,0,0, 1,1,1,1,1,1,1, 2,2,2,2,2,2,
                                  3,3,3,3,3, 4,4,4,4, 5,5,5, 6,6, 7};
__device__ const int TRI_J[36] = {0,1,2,3,4,5,6,7, 1,2,3,4,5,6,7, 2,3,4,5,6,7,
                                  3,4,5,6,7, 4,5,6,7, 5,6,7, 6,7, 7};

__global__ void __launch_bounds__(64) k_pair(
    const float* __restrict__ rp0, const float* __restrict__ rp1,
    const float* __restrict__ rp2, const float* __restrict__ rp3,
    const float* __restrict__ times, const float* __restrict__ now_time,
    const int* __restrict__ qs, const int* __restrict__ qd, int B, int E) {
    int pair = blockIdx.x;
    if (pair >= B) return;
    int tid = threadIdx.x;           // 0..63 (column slice)
    int lane = tid & 31, wid = tid >> 5;

    __shared__ float sh_part[2][36];
    __shared__ float sh_feat[64];

    int s = qs[pair];
    int t = qd[pair];
    float d = __expf(-WDECAY * (__ldg(times + E - 1) - __ldg(now_time)));
    float d2 = d * d;
    float d3 = d2 * d;

    const float4* r0 = (const float4*)rp0;
    const float4* r1 = (const float4*)rp1;
    const float4* r2 = (const float4*)rp2;
    const float4* r3 = (const float4*)rp3;

    size_t so = (size_t)s * ROW4 + tid;
    size_t to = (size_t)t * ROW4 + tid;

    float4 acc[8];
    acc[0] = __ldg(r0 + so);
    acc[1] = f4s(__ldg(r1 + so), d);
    acc[2] = f4s(__ldg(r2 + so), d2);
    acc[3] = f4s(__ldg(r3 + so), d3);
    acc[4] = __ldg(r0 + to);
    acc[5] = f4s(__ldg(r1 + to), d);
    acc[6] = f4s(__ldg(r2 + to), d2);
    acc[7] = f4s(__ldg(r3 + to), d3);

#pragma unroll
    for (int side = 0; side < 2; side++) {
        int v = side ? t : s;
        int base = side * 4;
        int g = min(__ldg(&g_deg[v]), CAP);
        const int2* adj = g_adj + (size_t)v * CAP;
        int2 a_next;
        if (g > 0) a_next = __ldg(adj);
        for (int j = 0; j < g; j++) {
            int2 a = a_next;
            if (j + 1 < g) a_next = __ldg(adj + j + 1);
            int u = a.x;
            float w = __int_as_float(a.y);
            size_t uo = (size_t)u * ROW4 + tid;
            float4 x0 = __ldg(r0 + uo);
            float4 x1 = __ldg(r1 + uo);
            float4 x2 = __ldg(r2 + uo);
            float w1c = w;
            float w2c = w * d;
            float w3c = w * d2;
            acc[base + 1].x += w1c * x0.x; acc[base + 1].y += w1c * x0.y;
            acc[base + 1].z += w1c * x0.z; acc[base + 1].w += w1c * x0.w;
            acc[base + 2].x += w2c * x1.x; acc[base + 2].y += w2c * x1.y;
            acc[base + 2].z += w2c * x1.z; acc[base + 2].w += w2c * x1.w;
            acc[base + 3].x += w3c * x2.x; acc[base + 3].y += w3c * x2.y;
            acc[base + 3].z += w3c * x2.z; acc[base + 3].w += w3c * x2.w;
        }
    }

#pragma unroll
    for (int i = 0; i < 8; i++) {
#pragma unroll
        for (int j = i; j < 8; j++) {
            const int idx = i * 8 - (i * (i - 1)) / 2 + (j - i);
            float p = acc[i].x * acc[j].x + acc[i].y * acc[j].y +
                      acc[i].z * acc[j].z + acc[i].w * acc[j].w;
            p += __shfl_xor_sync(0xFFFFFFFF, p, 16);
            p += __shfl_xor_sync(0xFFFFFFFF, p, 8);
            p += __shfl_xor_sync(0xFFFFFFFF, p, 4);
            p += __shfl_xor_sync(0xFFFFFFFF, p, 2);
            p += __shfl_xor_sync(0xFFFFFFFF, p, 1);
            if (lane == 0) sh_part[wid][idx] = p;
        }
    }
    __syncthreads();
    if (tid < 36) {
        float v = sh_part[0][tid] + sh_part[1][tid];
        v = log1pf(fmaxf(v, 0.0f));
        int i = TRI_I[tid], j = TRI_J[tid];
        sh_feat[i * 8 + j] = v;
        sh_feat[j * 8 + i] = v;
    }
    __syncthreads();

    // write feat value tid (col of this pair) into A-fragment layout
    {
        unsigned tv = f2tf32(sh_feat[tid]);
        int grp = pair >> 4, r = pair & 15;
        int gq = r & 7, half = r >> 3;
        int k8 = tid >> 3, ct = tid & 7;
        int tq = ct & 3, hi = ct >> 2;
        int m = half + 2 * hi;        // 0:a0 1:a1 2:a2 3:a3
        unsigned* dstp = (unsigned*)(g_featf + ((size_t)grp * 8 + k8) * 32 +
                                     (gq * 4 + tq));
        dstp[m] = tv;
    }
}

// ---------------------------------------------------------------------------
// Lean MLP: hoisted A fragments (R11) + GEMM1 n8 split in two halves of 4
// to cut dA register pressure 32->16, targeting 6 blocks/SM.
// ---------------------------------------------------------------------------
__global__ void __launch_bounds__(128, 6) k_mlp(
    const float* __restrict__ b1, const float* __restrict__ b2,
    float* __restrict__ out, int B) {
    __shared__ unsigned sR[4][16 * 68];
    int lane = threadIdx.x & 31;
    int warp = threadIdx.x >> 5;
    int grp = blockIdx.x * 4 + warp;
    int ngrp = (B + 15) >> 4;
    if (grp >= ngrp) return;
    int gq = lane >> 2, tq = lane & 3;
    unsigned* sRw = sR[warp];

    float o0[8], o1[8], o2[8], o3[8];
#pragma unroll
    for (int n8 = 0; n8 < 8; n8++) { o0[n8] = o1[n8] = o2[n8] = o3[n8] = 0.f; }

    const uint4* featf = g_featf + (size_t)grp * 8 * 32 + lane;

    // hoist GEMM1 A fragments (16 rows x K=64)
    uint4 aF[8];
#pragma unroll
    for (int k8 = 0; k8 < 8; k8++) aF[k8] = __ldg(featf + k8 * 32);

#pragma unroll
    for (int c = 0; c < 4; c++) {
        // ---- GEMM1 chunk in two n8-halves of 4 (dA = 16 regs) ----
#pragma unroll
        for (int h = 0; h < 2; h++) {
            float dA[4][4];
#pragma unroll
            for (int n4 = 0; n4 < 4; n4++)
                dA[n4][0] = dA[n4][1] = dA[n4][2] = dA[n4][3] = 0.f;
#pragma unroll
            for (int k8 = 0; k8 < 8; k8++) {
#pragma unroll
                for (int n4 = 0; n4 < 4; n4++) {
                    int n8 = h * 4 + n4;
                    uint2 b = __ldg(&g_w1f[((k8 * 32 + c * 8 + n8) * 32 + lane)]);
                    MMA_TF32(dA[n4][0], dA[n4][1], dA[n4][2], dA[n4][3],
                             aF[k8].x, aF[k8].y, aF[k8].z, aF[k8].w, b.x, b.y);
                }
            }
            // bias + relu -> per-warp smem (tf32 bits)
#pragma unroll
            for (int n4 = 0; n4 < 4; n4++) {
                int n8 = h * 4 + n4;
                float bb0 = __ldg(b1 + c * 64 + n8 * 8 + 2 * tq);
                float bb1 = __ldg(b1 + c * 64 + n8 * 8 + 2 * tq + 1);
                sRw[gq * 68 + n8 * 8 + 2 * tq]     = f2tf32(fmaxf(dA[n4][0] + bb0, 0.f));
                sRw[gq * 68 + n8 * 8 + 2 * tq + 1] = f2tf32(fmaxf(dA[n4][1] + bb1, 0.f));
                sRw[(gq + 8) * 68 + n8 * 8 + 2 * tq]     = f2tf32(fmaxf(dA[n4][2] + bb0, 0.f));
                sRw[(gq + 8) * 68 + n8 * 8 + 2 * tq + 1] = f2tf32(fmaxf(dA[n4][3] + bb1, 0.f));
            }
        }
        __syncwarp();

        // ---- GEMM2 chunk: o += h_chunk @ w2[c*64 : c*64+64, :] ----
#pragma unroll
        for (int k8 = 0; k8 < 8; k8++) {
            unsigned a0 = sRw[gq * 68 + k8 * 8 + tq];
            unsigned a1 = sRw[(gq + 8) * 68 + k8 * 8 + tq];
            unsigned a2 = sRw[gq * 68 + k8 * 8 + tq + 4];
            unsigned a3 = sRw[(gq + 8) * 68 + k8 * 8 + tq + 4];
#pragma unroll
            for (int n8 = 0; n8 < 8; n8++) {
                uint2 b = __ldg(&g_w2f[((c * 8 + k8) * 8 + n8) * 32 + lane]);
                MMA_TF32(o0[n8], o1[n8], o2[n8], o3[n8],
                         a0, a1, a2, a3, b.x, b.y);
            }
        }
        __syncwarp();
    }

    // ---- epilogue: + b2, store ----
#pragma unroll
    for (int n8 = 0; n8 < 8; n8++) {
        float bb0 = __ldg(b2 + n8 * 8 + 2 * tq);
        float bb1 = __ldg(b2 + n8 * 8 + 2 * tq + 1);
        int r0i = grp * 16 + gq;
        int r1i = r0i + 8;
        if (r0i < B) {
            float2 v = make_float2(o0[n8] + bb0, o1[n8] + bb1);
            *(float2*)(out + (size_t)r0i * 64 + n8 * 8 + 2 * tq) = v;
        }
        if (r1i < B) {
            float2 v = make_float2(o2[n8] + bb0, o3[n8] + bb1);
            *(float2*)(out + (size_t)r1i * 64 + n8 * 8 + 2 * tq) = v;
        }
    }
}

// ---------------------------------------------------------------------------
extern "C" void kernel_launch(void* const* d_in, const int* in_sizes, int n_in,
                              void* d_out, int out_size) {
    const float* rp0      = (const float*)d_in[0];
    const float* rp1      = (const float*)d_in[1];
    const float* rp2      = (const float*)d_in[2];
    const float* rp3      = (const float*)d_in[3];
    const float* times    = (const float*)d_in[4];
    const float* now_time = (const float*)d_in[5];
    const float* w1       = (const float*)d_in[6];
    const float* b1       = (const float*)d_in[7];
    const float* w2       = (const float*)d_in[8];
    const float* b2       = (const float*)d_in[9];
    const int*   src      = (const int*)d_in[10];
    const int*   dst      = (const int*)d_in[11];
    const int*   qs       = (const int*)d_in[12];
    const int*   qd       = (const int*)d_in[13];

    int E = in_sizes[4];
    int B = in_sizes[12];
    int ngrp = (B + 15) / 16;
    int mlp_blocks = (ngrp + 3) / 4;

    int init_threads = 25000 + 512 * 32;
    k_init<<<(init_threads + 255) / 256, 256>>>(w1, w2);
    k_build<<<(E + 255) / 256, 256>>>(src, dst, times, E);
    k_pair<<<B, 64>>>(rp0, rp1, rp2, rp3, times, now_time, qs, qd, B, E);
    k_mlp<<<mlp_blocks, 128>>>(b1, b2, (float*)d_out, B);
}

// round 15
// speedup vs baseline: 1.0937x; 1.0937x over previous
#include <cuda_runtime.h>
#include <math.h>

// Fixed problem shapes
#define NN 100000
#define DD 256
#define EE 200000
#define BB 50000
#define WDECAY 1e-6f
#define ROW4 (DD / 4)   // 64 float4 per row
#define CAP 48          // max incident edges per node (Poisson(4); P(>48) ~ 0)
#define NGRP ((BB + 15) / 16 + 2)

// Scratch (device globals — no runtime allocation allowed)
__device__ int   g_deg[NN];
__device__ int2  g_adj[(size_t)NN * CAP];        // {opp_node, float_bits(tw)}
__device__ uint4 g_featf[(size_t)NGRP * 8 * 32]; // feat in A-fragment tf32 layout
__device__ uint2 g_w1f[256 * 32];                // w1 B-fragments
__device__ uint2 g_w2f[256 * 32];                // w2 B-fragments

__device__ __forceinline__ float4 f4s(float4 a, float s) {
    return make_float4(a.x * s, a.y * s, a.z * s, a.w * s);
}

__device__ __forceinline__ unsigned f2tf32(float x) {
    unsigned r;
    asm("cvt.rna.tf32.f32 %0, %1;" : "=r"(r) : "f"(x));
    return r;
}

#define MMA_TF32(d0, d1, d2, d3, a0, a1, a2, a3, b0, b1)                     \
    asm("mma.sync.aligned.m16n8k8.row.col.f32.tf32.tf32.f32 "                \
        "{%0,%1,%2,%3}, {%4,%5,%6,%7}, {%8,%9}, {%0,%1,%2,%3};"              \
        : "+f"(d0), "+f"(d1), "+f"(d2), "+f"(d3)                             \
        : "r"(a0), "r"(a1), "r"(a2), "r"(a3), "r"(b0), "r"(b1))

// ---------------------------------------------------------------------------
// k_init: zero g_deg + prep w1/w2 fragments, role by index.
// ---------------------------------------------------------------------------
__global__ void k_init(const float* __restrict__ w1,
                       const float* __restrict__ w2) {
    int i = blockIdx.x * blockDim.x + threadIdx.x;
    if (i < 25000) {
        ((int4*)g_deg)[i] = make_int4(0, 0, 0, 0);
        return;
    }
    i -= 25000;
    if (i >= 512 * 32) return;
    int lane = i & 31, frag = i >> 5;
    int gq = lane >> 2, tq = lane & 3;
    if (frag < 256) {
        int k8 = frag >> 5, nc = frag & 31;
        float b0 = __ldg(w1 + (k8 * 8 + tq) * 256 + nc * 8 + gq);
        float b1 = __ldg(w1 + (k8 * 8 + tq + 4) * 256 + nc * 8 + gq);
        g_w1f[i] = make_uint2(f2tf32(b0), f2tf32(b1));
    } else {
        int f2 = frag - 256;
        int kk = f2 >> 3, n8 = f2 & 7;
        float b0 = __ldg(w2 + (kk * 8 + tq) * 64 + n8 * 8 + gq);
        float b1 = __ldg(w2 + (kk * 8 + tq + 4) * 64 + n8 * 8 + gq);
        g_w2f[f2 * 32 + lane] = make_uint2(f2tf32(b0), f2tf32(b1));
    }
}

// ---------------------------------------------------------------------------
// Build padded adjacency in one pass (scalars folded in)
// ---------------------------------------------------------------------------
__global__ void k_build(const int* __restrict__ src,
                        const int* __restrict__ dst,
                        const float* __restrict__ times, int E) {
    int e = blockIdx.x * blockDim.x + threadIdx.x;
    if (e >= E) return;
    float nt = __ldg(times + E - 1);
    int s = src[e];
    int t = dst[e];
    float w = expf(-WDECAY * (nt - times[e]));
    int wb = __float_as_int(w);
    int p1 = atomicAdd(&g_deg[s], 1);
    if (p1 < CAP) g_adj[(size_t)s * CAP + p1] = make_int2(t, wb);
    int p2 = atomicAdd(&g_deg[t], 1);
    if (p2 < CAP) g_adj[(size_t)t * CAP + p2] = make_int2(s, wb);
}

// ---------------------------------------------------------------------------
// Fused pair kernel (best-measured body): 64 threads/pair, float4 column
// slices. Computes the 8 updated rows for (s,t) on the fly, Gram + log1p,
// then writes feat directly in A-fragment tf32 layout -> g_featf.
// ---------------------------------------------------------------------------
__device__ const int TRI_I[36] = {0,0,0,0,0,0,0,0, 1,1,1,1,1,1,1, 2,2,2,2,2,2,
                                  3,3,3,3,3, 4,4,4,4, 5,5,5, 6,6, 7};
__device__ const int TRI_J[36] = {0,1,2,3,4,5,6,7, 1,2,3,4,5,6,7, 2,3,4,5,6,7,
                                  3,4,5,6,7, 4,5,6,7, 5,6,7, 6,7, 7};

__global__ void __launch_bounds__(64) k_pair(
    const float* __restrict__ rp0, const float* __restrict__ rp1,
    const float* __restrict__ rp2, const float* __restrict__ rp3,
    const float* __restrict__ times, const float* __restrict__ now_time,
    const int* __restrict__ qs, const int* __restrict__ qd, int B, int E) {
    int pair = blockIdx.x;
    if (pair >= B) return;
    int tid = threadIdx.x;           // 0..63 (column slice)
    int lane = tid & 31, wid = tid >> 5;

    __shared__ float sh_part[2][36];
    __shared__ float sh_feat[64];

    int s = qs[pair];
    int t = qd[pair];
    float d = expf(-WDECAY * (__ldg(times + E - 1) - __ldg(now_time)));
    float d2 = d * d;
    float d3 = d2 * d;

    const float4* r0 = (const float4*)rp0;
    const float4* r1 = (const float4*)rp1;
    const float4* r2 = (const float4*)rp2;
    const float4* r3 = (const float4*)rp3;

    size_t so = (size_t)s * ROW4 + tid;
    size_t to = (size_t)t * ROW4 + tid;

    float4 acc[8];
    acc[0] = __ldg(r0 + so);
    acc[1] = f4s(__ldg(r1 + so), d);
    acc[2] = f4s(__ldg(r2 + so), d2);
    acc[3] = f4s(__ldg(r3 + so), d3);
    acc[4] = __ldg(r0 + to);
    acc[5] = f4s(__ldg(r1 + to), d);
    acc[6] = f4s(__ldg(r2 + to), d2);
    acc[7] = f4s(__ldg(r3 + to), d3);

#pragma unroll
    for (int side = 0; side < 2; side++) {
        int v = side ? t : s;
        int base = side * 4;
        int g = min(__ldg(&g_deg[v]), CAP);
        const int2* adj = g_adj + (size_t)v * CAP;
        int2 a_next;
        if (g > 0) a_next = __ldg(adj);
        for (int j = 0; j < g; j++) {
            int2 a = a_next;
            if (j + 1 < g) a_next = __ldg(adj + j + 1);
            int u = a.x;
            float w = __int_as_float(a.y);
            size_t uo = (size_t)u * ROW4 + tid;
            float4 x0 = __ldg(r0 + uo);
            float4 x1 = __ldg(r1 + uo);
            float4 x2 = __ldg(r2 + uo);
            float w1c = w;
            float w2c = w * d;
            float w3c = w * d2;
            acc[base + 1].x += w1c * x0.x; acc[base + 1].y += w1c * x0.y;
            acc[base + 1].z += w1c * x0.z; acc[base + 1].w += w1c * x0.w;
            acc[base + 2].x += w2c * x1.x; acc[base + 2].y += w2c * x1.y;
            acc[base + 2].z += w2c * x1.z; acc[base + 2].w += w2c * x1.w;
            acc[base + 3].x += w3c * x2.x; acc[base + 3].y += w3c * x2.y;
            acc[base + 3].z += w3c * x2.z; acc[base + 3].w += w3c * x2.w;
        }
    }

#pragma unroll
    for (int i = 0; i < 8; i++) {
#pragma unroll
        for (int j = i; j < 8; j++) {
            const int idx = i * 8 - (i * (i - 1)) / 2 + (j - i);
            float p = acc[i].x * acc[j].x + acc[i].y * acc[j].y +
                      acc[i].z * acc[j].z + acc[i].w * acc[j].w;
            p += __shfl_xor_sync(0xFFFFFFFF, p, 16);
            p += __shfl_xor_sync(0xFFFFFFFF, p, 8);
            p += __shfl_xor_sync(0xFFFFFFFF, p, 4);
            p += __shfl_xor_sync(0xFFFFFFFF, p, 2);
            p += __shfl_xor_sync(0xFFFFFFFF, p, 1);
            if (lane == 0) sh_part[wid][idx] = p;
        }
    }
    __syncthreads();
    if (tid < 36) {
        float v = sh_part[0][tid] + sh_part[1][tid];
        v = log1pf(fmaxf(v, 0.0f));
        int i = TRI_I[tid], j = TRI_J[tid];
        sh_feat[i * 8 + j] = v;
        sh_feat[j * 8 + i] = v;
    }
    __syncthreads();

    // write feat value tid (col of this pair) into A-fragment layout
    {
        unsigned tv = f2tf32(sh_feat[tid]);
        int grp = pair >> 4, r = pair & 15;
        int gq = r & 7, half = r >> 3;
        int k8 = tid >> 3, ct = tid & 7;
        int tq = ct & 3, hi = ct >> 2;
        int m = half + 2 * hi;        // 0:a0 1:a1 2:a2 3:a3
        unsigned* dstp = (unsigned*)(g_featf + ((size_t)grp * 8 + k8) * 32 +
                                     (gq * 4 + tq));
        dstp[m] = tv;
    }
}

// ---------------------------------------------------------------------------
// Lean MLP (R11 configuration — best measured): 128 threads = 4 warps, each
// warp owns 16 rows end-to-end; hoisted A fragments; plain grid.
// ---------------------------------------------------------------------------
__global__ void __launch_bounds__(128, 4) k_mlp(
    const float* __restrict__ b1, const float* __restrict__ b2,
    float* __restrict__ out, int B) {
    __shared__ unsigned sR[4][16 * 68];
    int lane = threadIdx.x & 31;
    int warp = threadIdx.x >> 5;
    int grp = blockIdx.x * 4 + warp;
    int ngrp = (B + 15) >> 4;
    if (grp >= ngrp) return;
    int gq = lane >> 2, tq = lane & 3;
    unsigned* sRw = sR[warp];

    float o0[8], o1[8], o2[8], o3[8];
#pragma unroll
    for (int n8 = 0; n8 < 8; n8++) { o0[n8] = o1[n8] = o2[n8] = o3[n8] = 0.f; }

    const uint4* featf = g_featf + (size_t)grp * 8 * 32 + lane;

    // hoist GEMM1 A fragments (16 rows x K=64)
    uint4 aF[8];
#pragma unroll
    for (int k8 = 0; k8 < 8; k8++) aF[k8] = __ldg(featf + k8 * 32);

#pragma unroll
    for (int c = 0; c < 4; c++) {
        // ---- GEMM1 chunk: dA = feat @ w1[:, c*64 : c*64+64] ----
        float dA[8][4];
#pragma unroll
        for (int n8 = 0; n8 < 8; n8++)
            dA[n8][0] = dA[n8][1] = dA[n8][2] = dA[n8][3] = 0.f;
#pragma unroll
        for (int k8 = 0; k8 < 8; k8++) {
#pragma unroll
            for (int n8 = 0; n8 < 8; n8++) {
                uint2 b = __ldg(&g_w1f[((k8 * 32 + c * 8 + n8) * 32 + lane)]);
                MMA_TF32(dA[n8][0], dA[n8][1], dA[n8][2], dA[n8][3],
                         aF[k8].x, aF[k8].y, aF[k8].z, aF[k8].w, b.x, b.y);
            }
        }
        // bias + relu -> per-warp smem (tf32 bits)
#pragma unroll
        for (int n8 = 0; n8 < 8; n8++) {
            float bb0 = __ldg(b1 + c * 64 + n8 * 8 + 2 * tq);
            float bb1 = __ldg(b1 + c * 64 + n8 * 8 + 2 * tq + 1);
            sRw[gq * 68 + n8 * 8 + 2 * tq]     = f2tf32(fmaxf(dA[n8][0] + bb0, 0.f));
            sRw[gq * 68 + n8 * 8 + 2 * tq + 1] = f2tf32(fmaxf(dA[n8][1] + bb1, 0.f));
            sRw[(gq + 8) * 68 + n8 * 8 + 2 * tq]     = f2tf32(fmaxf(dA[n8][2] + bb0, 0.f));
            sRw[(gq + 8) * 68 + n8 * 8 + 2 * tq + 1] = f2tf32(fmaxf(dA[n8][3] + bb1, 0.f));
        }
        __syncwarp();

        // ---- GEMM2 chunk: o += h_chunk @ w2[c*64 : c*64+64, :] ----
#pragma unroll
        for (int k8 = 0; k8 < 8; k8++) {
            unsigned a0 = sRw[gq * 68 + k8 * 8 + tq];
            unsigned a1 = sRw[(gq + 8) * 68 + k8 * 8 + tq];
            unsigned a2 = sRw[gq * 68 + k8 * 8 + tq + 4];
            unsigned a3 = sRw[(gq + 8) * 68 + k8 * 8 + tq + 4];
#pragma unroll
            for (int n8 = 0; n8 < 8; n8++) {
                uint2 b = __ldg(&g_w2f[((c * 8 + k8) * 8 + n8) * 32 + lane]);
                MMA_TF32(o0[n8], o1[n8], o2[n8], o3[n8],
                         a0, a1, a2, a3, b.x, b.y);
            }
        }
        __syncwarp();
    }

    // ---- epilogue: + b2, store ----
#pragma unroll
    for (int n8 = 0; n8 < 8; n8++) {
        float bb0 = __ldg(b2 + n8 * 8 + 2 * tq);
        float bb1 = __ldg(b2 + n8 * 8 + 2 * tq + 1);
        int r0i = grp * 16 + gq;
        int r1i = r0i + 8;
        if (r0i < B) {
            float2 v = make_float2(o0[n8] + bb0, o1[n8] + bb1);
            *(float2*)(out + (size_t)r0i * 64 + n8 * 8 + 2 * tq) = v;
        }
        if (r1i < B) {
            float2 v = make_float2(o2[n8] + bb0, o3[n8] + bb1);
            *(float2*)(out + (size_t)r1i * 64 + n8 * 8 + 2 * tq) = v;
        }
    }
}

// ---------------------------------------------------------------------------
extern "C" void kernel_launch(void* const* d_in, const int* in_sizes, int n_in,
                              void* d_out, int out_size) {
    const float* rp0      = (const float*)d_in[0];
    const float* rp1      = (const float*)d_in[1];
    const float* rp2      = (const float*)d_in[2];
    const float* rp3      = (const float*)d_in[3];
    const float* times    = (const float*)d_in[4];
    const float* now_time = (const float*)d_in[5];
    const float* w1       = (const float*)d_in[6];
    const float* b1       = (const float*)d_in[7];
    const float* w2       = (const float*)d_in[8];
    const float* b2       = (const float*)d_in[9];
    const int*   src      = (const int*)d_in[10];
    const int*   dst      = (const int*)d_in[11];
    const int*   qs       = (const int*)d_in[12];
    const int*   qd       = (const int*)d_in[13];

    int E = in_sizes[4];
    int B = in_sizes[12];
    int ngrp = (B + 15) / 16;
    int mlp_blocks = (ngrp + 3) / 4;

    int init_threads = 25000 + 512 * 32;
    k_init<<<(init_threads + 255) / 256, 256>>>(w1, w2);
    k_build<<<(E + 255) / 256, 256>>>(src, dst, times, E);
    k_pair<<<B, 64>>>(rp0, rp1, rp2, rp3, times, now_time, qs, qd, B, E);
    k_mlp<<<mlp_blocks, 128>>>(b1, b2, (float*)d_out, B);
}

// round 16
// speedup vs baseline: 1.1038x; 1.0092x over previous
#include <cuda_runtime.h>
#include <math.h>

// Fixed problem shapes
#define NN 100000
#define DD 256
#define EE 200000
#define BB 50000
#define WDECAY 1e-6f
#define ROW4 (DD / 4)   // 64 float4 per row
#define CAP 48          // max incident edges per node (Poisson(4); P(>48) ~ 0)
#define NGRP ((BB + 15) / 16 + 2)

// Scratch (device globals — no runtime allocation allowed)
__device__ int   g_deg[NN];
__device__ int2  g_adj[(size_t)NN * CAP];        // {opp_node, float_bits(tw)}
__device__ uint4 g_featf[(size_t)NGRP * 8 * 32]; // feat in A-fragment tf32 layout
__device__ uint2 g_w1f[256 * 32];                // w1 B-fragments
__device__ uint2 g_w2f[256 * 32];                // w2 B-fragments

__device__ __forceinline__ float4 f4s(float4 a, float s) {
    return make_float4(a.x * s, a.y * s, a.z * s, a.w * s);
}

__device__ __forceinline__ unsigned f2tf32(float x) {
    unsigned r;
    asm("cvt.rna.tf32.f32 %0, %1;" : "=r"(r) : "f"(x));
    return r;
}

#define MMA_TF32(d0, d1, d2, d3, a0, a1, a2, a3, b0, b1)                     \
    asm("mma.sync.aligned.m16n8k8.row.col.f32.tf32.tf32.f32 "                \
        "{%0,%1,%2,%3}, {%4,%5,%6,%7}, {%8,%9}, {%0,%1,%2,%3};"              \
        : "+f"(d0), "+f"(d1), "+f"(d2), "+f"(d3)                             \
        : "r"(a0), "r"(a1), "r"(a2), "r"(a3), "r"(b0), "r"(b1))

// ---------------------------------------------------------------------------
// k_init: zero g_deg + prep w1/w2 fragments, role by index.
// ---------------------------------------------------------------------------
__global__ void k_init(const float* __restrict__ w1,
                       const float* __restrict__ w2) {
    int i = blockIdx.x * blockDim.x + threadIdx.x;
    if (i < 25000) {
        ((int4*)g_deg)[i] = make_int4(0, 0, 0, 0);
        return;
    }
    i -= 25000;
    if (i >= 512 * 32) return;
    int lane = i & 31, frag = i >> 5;
    int gq = lane >> 2, tq = lane & 3;
    if (frag < 256) {
        int k8 = frag >> 5, nc = frag & 31;
        float b0 = __ldg(w1 + (k8 * 8 + tq) * 256 + nc * 8 + gq);
        float b1 = __ldg(w1 + (k8 * 8 + tq + 4) * 256 + nc * 8 + gq);
        g_w1f[i] = make_uint2(f2tf32(b0), f2tf32(b1));
    } else {
        int f2 = frag - 256;
        int kk = f2 >> 3, n8 = f2 & 7;
        float b0 = __ldg(w2 + (kk * 8 + tq) * 64 + n8 * 8 + gq);
        float b1 = __ldg(w2 + (kk * 8 + tq + 4) * 64 + n8 * 8 + gq);
        g_w2f[f2 * 32 + lane] = make_uint2(f2tf32(b0), f2tf32(b1));
    }
}

// ---------------------------------------------------------------------------
// Build padded adjacency in one pass (scalars folded in)
// ---------------------------------------------------------------------------
__global__ void k_build(const int* __restrict__ src,
                        const int* __restrict__ dst,
                        const float* __restrict__ times, int E) {
    int e = blockIdx.x * blockDim.x + threadIdx.x;
    if (e >= E) return;
    float nt = __ldg(times + E - 1);
    int s = src[e];
    int t = dst[e];
    float w = expf(-WDECAY * (nt - times[e]));
    int wb = __float_as_int(w);
    int p1 = atomicAdd(&g_deg[s], 1);
    if (p1 < CAP) g_adj[(size_t)s * CAP + p1] = make_int2(t, wb);
    int p2 = atomicAdd(&g_deg[t], 1);
    if (p2 < CAP) g_adj[(size_t)t * CAP + p2] = make_int2(s, wb);
}

// ---------------------------------------------------------------------------
// Fused pair kernel (best-measured body): 64 threads/pair, float4 column
// slices. Computes the 8 updated rows for (s,t) on the fly, Gram + log1p,
// then writes feat directly in A-fragment tf32 layout -> g_featf.
// ---------------------------------------------------------------------------
__device__ const int TRI_I[36] = {0,0,0,0,0,0,0,0, 1,1,1,1,1,1,1, 2,2,2,2,2,2,
                                  3,3,3,3,3, 4,4,4,4, 5,5,5, 6,6, 7};
__device__ const int TRI_J[36] = {0,1,2,3,4,5,6,7, 1,2,3,4,5,6,7, 2,3,4,5,6,7,
                                  3,4,5,6,7, 4,5,6,7, 5,6,7, 6,7, 7};

__global__ void __launch_bounds__(64) k_pair(
    const float* __restrict__ rp0, const float* __restrict__ rp1,
    const float* __restrict__ rp2, const float* __restrict__ rp3,
    const float* __restrict__ times, const float* __restrict__ now_time,
    const int* __restrict__ qs, const int* __restrict__ qd, int B, int E) {
    int pair = blockIdx.x;
    if (pair >= B) return;
    int tid = threadIdx.x;           // 0..63 (column slice)
    int lane = tid & 31, wid = tid >> 5;

    __shared__ float sh_part[2][36];
    __shared__ float sh_feat[64];

    int s = qs[pair];
    int t = qd[pair];
    float d = expf(-WDECAY * (__ldg(times + E - 1) - __ldg(now_time)));
    float d2 = d * d;
    float d3 = d2 * d;

    const float4* r0 = (const float4*)rp0;
    const float4* r1 = (const float4*)rp1;
    const float4* r2 = (const float4*)rp2;
    const float4* r3 = (const float4*)rp3;

    size_t so = (size_t)s * ROW4 + tid;
    size_t to = (size_t)t * ROW4 + tid;

    float4 acc[8];
    acc[0] = __ldg(r0 + so);
    acc[1] = f4s(__ldg(r1 + so), d);
    acc[2] = f4s(__ldg(r2 + so), d2);
    acc[3] = f4s(__ldg(r3 + so), d3);
    acc[4] = __ldg(r0 + to);
    acc[5] = f4s(__ldg(r1 + to), d);
    acc[6] = f4s(__ldg(r2 + to), d2);
    acc[7] = f4s(__ldg(r3 + to), d3);

#pragma unroll
    for (int side = 0; side < 2; side++) {
        int v = side ? t : s;
        int base = side * 4;
        int g = min(__ldg(&g_deg[v]), CAP);
        const int2* adj = g_adj + (size_t)v * CAP;
        int2 a_next;
        if (g > 0) a_next = __ldg(adj);
        for (int j = 0; j < g; j++) {
            int2 a = a_next;
            if (j + 1 < g) a_next = __ldg(adj + j + 1);
            int u = a.x;
            float w = __int_as_float(a.y);
            size_t uo = (size_t)u * ROW4 + tid;
            float4 x0 = __ldg(r0 + uo);
            float4 x1 = __ldg(r1 + uo);
            float4 x2 = __ldg(r2 + uo);
            float w1c = w;
            float w2c = w * d;
            float w3c = w * d2;
            acc[base + 1].x += w1c * x0.x; acc[base + 1].y += w1c * x0.y;
            acc[base + 1].z += w1c * x0.z; acc[base + 1].w += w1c * x0.w;
            acc[base + 2].x += w2c * x1.x; acc[base + 2].y += w2c * x1.y;
            acc[base + 2].z += w2c * x1.z; acc[base + 2].w += w2c * x1.w;
            acc[base + 3].x += w3c * x2.x; acc[base + 3].y += w3c * x2.y;
            acc[base + 3].z += w3c * x2.z; acc[base + 3].w += w3c * x2.w;
        }
    }

#pragma unroll
    for (int i = 0; i < 8; i++) {
#pragma unroll
        for (int j = i; j < 8; j++) {
            const int idx = i * 8 - (i * (i - 1)) / 2 + (j - i);
            float p = acc[i].x * acc[j].x + acc[i].y * acc[j].y +
                      acc[i].z * acc[j].z + acc[i].w * acc[j].w;
            p += __shfl_xor_sync(0xFFFFFFFF, p, 16);
            p += __shfl_xor_sync(0xFFFFFFFF, p, 8);
            p += __shfl_xor_sync(0xFFFFFFFF, p, 4);
            p += __shfl_xor_sync(0xFFFFFFFF, p, 2);
            p += __shfl_xor_sync(0xFFFFFFFF, p, 1);
            if (lane == 0) sh_part[wid][idx] = p;
        }
    }
    __syncthreads();
    if (tid < 36) {
        float v = sh_part[0][tid] + sh_part[1][tid];
        v = log1pf(fmaxf(v, 0.0f));
        int i = TRI_I[tid], j = TRI_J[tid];
        sh_feat[i * 8 + j] = v;
        sh_feat[j * 8 + i] = v;
    }
    __syncthreads();

    // write feat value tid (col of this pair) into A-fragment layout
    {
        unsigned tv = f2tf32(sh_feat[tid]);
        int grp = pair >> 4, r = pair & 15;
        int gq = r & 7, half = r >> 3;
        int k8 = tid >> 3, ct = tid & 7;
        int tq = ct & 3, hi = ct >> 2;
        int m = half + 2 * hi;        // 0:a0 1:a1 2:a2 3:a3
        unsigned* dstp = (unsigned*)(g_featf + ((size_t)grp * 8 + k8) * 32 +
                                     (gq * 4 + tq));
        dstp[m] = tv;
    }
}

// ---------------------------------------------------------------------------
// Lean MLP (best measured): 128 threads = 4 warps, each warp owns 16 rows
// end-to-end; hoisted A fragments; plain grid.
// ---------------------------------------------------------------------------
__global__ void __launch_bounds__(128, 4) k_mlp(
    const float* __restrict__ b1, const float* __restrict__ b2,
    float* __restrict__ out, int B) {
    __shared__ unsigned sR[4][16 * 68];
    int lane = threadIdx.x & 31;
    int warp = threadIdx.x >> 5;
    int grp = blockIdx.x * 4 + warp;
    int ngrp = (B + 15) >> 4;
    if (grp >= ngrp) return;
    int gq = lane >> 2, tq = lane & 3;
    unsigned* sRw = sR[warp];

    float o0[8], o1[8], o2[8], o3[8];
#pragma unroll
    for (int n8 = 0; n8 < 8; n8++) { o0[n8] = o1[n8] = o2[n8] = o3[n8] = 0.f; }

    const uint4* featf = g_featf + (size_t)grp * 8 * 32 + lane;

    // hoist GEMM1 A fragments (16 rows x K=64)
    uint4 aF[8];
#pragma unroll
    for (int k8 = 0; k8 < 8; k8++) aF[k8] = __ldg(featf + k8 * 32);

#pragma unroll
    for (int c = 0; c < 4; c++) {
        // ---- GEMM1 chunk: dA = feat @ w1[:, c*64 : c*64+64] ----
        float dA[8][4];
#pragma unroll
        for (int n8 = 0; n8 < 8; n8++)
            dA[n8][0] = dA[n8][1] = dA[n8][2] = dA[n8][3] = 0.f;
#pragma unroll
        for (int k8 = 0; k8 < 8; k8++) {
#pragma unroll
            for (int n8 = 0; n8 < 8; n8++) {
                uint2 b = __ldg(&g_w1f[((k8 * 32 + c * 8 + n8) * 32 + lane)]);
                MMA_TF32(dA[n8][0], dA[n8][1], dA[n8][2], dA[n8][3],
                         aF[k8].x, aF[k8].y, aF[k8].z, aF[k8].w, b.x, b.y);
            }
        }
        // bias + relu -> per-warp smem (tf32 bits)
#pragma unroll
        for (int n8 = 0; n8 < 8; n8++) {
            float bb0 = __ldg(b1 + c * 64 + n8 * 8 + 2 * tq);
            float bb1 = __ldg(b1 + c * 64 + n8 * 8 + 2 * tq + 1);
            sRw[gq * 68 + n8 * 8 + 2 * tq]     = f2tf32(fmaxf(dA[n8][0] + bb0, 0.f));
            sRw[gq * 68 + n8 * 8 + 2 * tq + 1] = f2tf32(fmaxf(dA[n8][1] + bb1, 0.f));
            sRw[(gq + 8) * 68 + n8 * 8 + 2 * tq]     = f2tf32(fmaxf(dA[n8][2] + bb0, 0.f));
            sRw[(gq + 8) * 68 + n8 * 8 + 2 * tq + 1] = f2tf32(fmaxf(dA[n8][3] + bb1, 0.f));
        }
        __syncwarp();

        // ---- GEMM2 chunk: o += h_chunk @ w2[c*64 : c*64+64, :] ----
#pragma unroll
        for (int k8 = 0; k8 < 8; k8++) {
            unsigned a0 = sRw[gq * 68 + k8 * 8 + tq];
            unsigned a1 = sRw[(gq + 8) * 68 + k8 * 8 + tq];
            unsigned a2 = sRw[gq * 68 + k8 * 8 + tq + 4];
            unsigned a3 = sRw[(gq + 8) * 68 + k8 * 8 + tq + 4];
#pragma unroll
            for (int n8 = 0; n8 < 8; n8++) {
                uint2 b = __ldg(&g_w2f[((c * 8 + k8) * 8 + n8) * 32 + lane]);
                MMA_TF32(o0[n8], o1[n8], o2[n8], o3[n8],
                         a0, a1, a2, a3, b.x, b.y);
            }
        }
        __syncwarp();
    }

    // ---- epilogue: + b2, store ----
#pragma unroll
    for (int n8 = 0; n8 < 8; n8++) {
        float bb0 = __ldg(b2 + n8 * 8 + 2 * tq);
        float bb1 = __ldg(b2 + n8 * 8 + 2 * tq + 1);
        int r0i = grp * 16 + gq;
        int r1i = r0i + 8;
        if (r0i < B) {
            float2 v = make_float2(o0[n8] + bb0, o1[n8] + bb1);
            *(float2*)(out + (size_t)r0i * 64 + n8 * 8 + 2 * tq) = v;
        }
        if (r1i < B) {
            float2 v = make_float2(o2[n8] + bb0, o3[n8] + bb1);
            *(float2*)(out + (size_t)r1i * 64 + n8 * 8 + 2 * tq) = v;
        }
    }
}

// ---------------------------------------------------------------------------
extern "C" void kernel_launch(void* const* d_in, const int* in_sizes, int n_in,
                              void* d_out, int out_size) {
    const float* rp0      = (const float*)d_in[0];
    const float* rp1      = (const float*)d_in[1];
    const float* rp2      = (const float*)d_in[2];
    const float* rp3      = (const float*)d_in[3];
    const float* times    = (const float*)d_in[4];
    const float* now_time = (const float*)d_in[5];
    const float* w1       = (const float*)d_in[6];
    const float* b1       = (const float*)d_in[7];
    const float* w2       = (const float*)d_in[8];
    const float* b2       = (const float*)d_in[9];
    const int*   src      = (const int*)d_in[10];
    const int*   dst      = (const int*)d_in[11];
    const int*   qs       = (const int*)d_in[12];
    const int*   qd       = (const int*)d_in[13];

    int E = in_sizes[4];
    int B = in_sizes[12];
    int ngrp = (B + 15) / 16;
    int mlp_blocks = (ngrp + 3) / 4;

    int init_threads = 25000 + 512 * 32;
    k_init<<<(init_threads + 255) / 256, 256>>>(w1, w2);
    k_build<<<(E + 255) / 256, 256>>>(src, dst, times, E);
    k_pair<<<B, 64>>>(rp0, rp1, rp2, rp3, times, now_time, qs, qd, B, E);
    k_mlp<<<mlp_blocks, 128>>>(b1, b2, (float*)d_out, B);
}